// round 1
// baseline (speedup 1.0000x reference)
#include <cuda_runtime.h>
#include <cstddef>

#define NIMG 8192
#define GFC 56
#define NBLK_FC ((NIMG + GFC - 1) / GFC)   /* 147 */
#define NPAD (NBLK_FC * GFC)               /* 8232 */

// Scratch activations after conv stage: [NPAD, 400] (padded tail stays zero).
__device__ float g_act[(size_t)NPAD * 400];

// ---------------------------------------------------------------------------
// Kernel 1: fused conv1 -> relu -> pool1 -> conv2 -> relu -> pool2
// One block per image, 128 threads. Only the live region is computed:
//   conv1 at 11x11, pool1 at 10x10, conv2 at 6x6, pool2 at 5x5.
// ---------------------------------------------------------------------------
__global__ __launch_bounds__(128) void conv_kernel(const float* __restrict__ x,
                                                   const float* __restrict__ w1,
                                                   const float* __restrict__ w2)
{
    __shared__ float s_w1[450];             // [6][3][5][5]
    __shared__ float s_w2[2400];            // [16][6][5][5]
    __shared__ float s_patch[3][15][16];    // input rows 0..14, cols 0..15
    __shared__ float s_c1[6][11][12];       // conv1 relu, 11x11 (padded)
    __shared__ float s_p1[6][10][12];       // pool1, 10x10 (padded)
    __shared__ float s_c2[16][6][8];        // conv2 relu, 6x6 (padded)

    const int tid = threadIdx.x;
    const int img = blockIdx.x;

    for (int i = tid; i < 450; i += 128) s_w1[i] = w1[i];
    for (int i = tid; i < 2400; i += 128) s_w2[i] = w2[i];

    const float* xb = x + (size_t)img * 3072;
    for (int i = tid; i < 3 * 15 * 16; i += 128) {
        int c = i / 240;
        int rr = (i % 240) / 16;
        int cc = i % 16;
        s_patch[c][rr][cc] = xb[c * 1024 + rr * 32 + cc];
    }
    __syncthreads();

    // conv1 + relu: tasks = oc(6) x row(11) x coltile(3, widths 4/4/3) = 198
    for (int task = tid; task < 198; task += 128) {
        int oc = task / 33;
        int rem = task % 33;
        int r  = rem / 3;
        int ct = rem % 3;
        int c0 = ct * 4;
        float acc0 = 0.f, acc1 = 0.f, acc2 = 0.f, acc3 = 0.f;
        for (int c = 0; c < 3; c++) {
            #pragma unroll
            for (int u = 0; u < 5; u++) {
                float p[8];
                #pragma unroll
                for (int j = 0; j < 8; j++) p[j] = s_patch[c][r + u][c0 + j];
                const float* wp = &s_w1[(oc * 3 + c) * 25 + u * 5];
                #pragma unroll
                for (int v = 0; v < 5; v++) {
                    float w = wp[v];
                    acc0 += p[v + 0] * w;
                    acc1 += p[v + 1] * w;
                    acc2 += p[v + 2] * w;
                    acc3 += p[v + 3] * w;
                }
            }
        }
        s_c1[oc][r][c0 + 0] = fmaxf(acc0, 0.f);
        s_c1[oc][r][c0 + 1] = fmaxf(acc1, 0.f);
        s_c1[oc][r][c0 + 2] = fmaxf(acc2, 0.f);
        if (ct < 2) s_c1[oc][r][c0 + 3] = fmaxf(acc3, 0.f);
    }
    __syncthreads();

    // pool1 (stride-1 2x2 max, top-left 10x10 region)
    for (int t = tid; t < 600; t += 128) {
        int oc = t / 100;
        int rr = (t % 100) / 10;
        int cc = t % 10;
        float m = fmaxf(fmaxf(s_c1[oc][rr][cc],     s_c1[oc][rr][cc + 1]),
                        fmaxf(s_c1[oc][rr + 1][cc], s_c1[oc][rr + 1][cc + 1]));
        s_p1[oc][rr][cc] = m;
    }
    __syncthreads();

    // conv2 + relu: tasks = oc(16) x row(6) = 96, each computes 6 cols
    if (tid < 96) {
        int oc = tid / 6;
        int r  = tid % 6;
        float acc[6] = {0.f, 0.f, 0.f, 0.f, 0.f, 0.f};
        for (int c = 0; c < 6; c++) {
            #pragma unroll
            for (int u = 0; u < 5; u++) {
                float p[10];
                #pragma unroll
                for (int j = 0; j < 10; j++) p[j] = s_p1[c][r + u][j];
                const float* wp = &s_w2[((oc * 6 + c) * 5 + u) * 5];
                #pragma unroll
                for (int v = 0; v < 5; v++) {
                    float w = wp[v];
                    #pragma unroll
                    for (int xj = 0; xj < 6; xj++) acc[xj] += p[v + xj] * w;
                }
            }
        }
        #pragma unroll
        for (int xj = 0; xj < 6; xj++) s_c2[oc][r][xj] = fmaxf(acc[xj], 0.f);
    }
    __syncthreads();

    // pool2 -> g_act (channel-major flatten: oc*25 + i*5 + j)
    for (int t = tid; t < 400; t += 128) {
        int oc = t / 25;
        int rr = (t % 25) / 5;
        int cc = t % 5;
        float m = fmaxf(fmaxf(s_c2[oc][rr][cc],     s_c2[oc][rr][cc + 1]),
                        fmaxf(s_c2[oc][rr + 1][cc], s_c2[oc][rr + 1][cc + 1]));
        g_act[(size_t)img * 400 + t] = m;
    }
}

// ---------------------------------------------------------------------------
// Kernel 2: fused fc1(relu) -> fc2(relu) -> fc3
// One block per 56 images (147 blocks = one wave), 512 threads.
// fc1 weights staged through shared in k-chunks of 50 (transposed for float4
// reads); fc2/fc3 weights fully shared-resident.
// ---------------------------------------------------------------------------
__global__ __launch_bounds__(512) void fc_kernel(const float* __restrict__ fw1,
                                                 const float* __restrict__ fb1,
                                                 const float* __restrict__ fw2,
                                                 const float* __restrict__ fb2,
                                                 const float* __restrict__ fw3,
                                                 const float* __restrict__ fb3,
                                                 float* __restrict__ out)
{
    extern __shared__ float sm[];
    float* s_act = sm;                       // GFC*400 = 22400
    float* s_w1c = s_act + GFC * 400;        // 50*120  = 6000 (transposed chunk)
    float* s_h1  = s_w1c + 6000;             // GFC*120 = 6720
    float* s_w2  = s_h1 + GFC * 120;         // 84*120  = 10080
    float* s_h2  = s_w2 + 84 * 120;          // GFC*84  = 4704
    float* s_w3  = s_h2 + GFC * 84;          // 10*84   = 840
    float* s_b1  = s_w3 + 840;               // 120
    float* s_b2  = s_b1 + 120;               // 84
    float* s_b3  = s_b2 + 84;                // 10

    const int tid = threadIdx.x;
    const int img0 = blockIdx.x * GFC;

    for (int i = tid; i < GFC * 400; i += 512)
        s_act[i] = g_act[(size_t)img0 * 400 + i];
    for (int i = tid; i < 10080; i += 512) s_w2[i] = fw2[i];
    for (int i = tid; i < 840; i += 512) s_w3[i] = fw3[i];
    if (tid < 120) s_b1[tid] = fb1[tid];
    if (tid < 84)  s_b2[tid] = fb2[tid];
    if (tid < 10)  s_b3[tid] = fb3[tid];

    // ---- fc1: [56,400] x [400,120]^T, 4x4 register tiles, 420 active threads
    const int ot = tid % 30;
    const int it = tid / 30;
    const int o0 = ot * 4;
    const int i0 = it * 4;
    float acc[16];
    #pragma unroll
    for (int i = 0; i < 16; i++) acc[i] = 0.f;

    for (int kc = 0; kc < 400; kc += 50) {
        __syncthreads();  // previous chunk consumers done (also covers s_act load)
        for (int i = tid; i < 6000; i += 512) {
            int o = i / 50, kk = i % 50;
            s_w1c[kk * 120 + o] = fw1[o * 400 + kc + kk];
        }
        __syncthreads();
        if (tid < 420) {
            #pragma unroll 5
            for (int kk = 0; kk < 50; kk++) {
                float4 w = *reinterpret_cast<const float4*>(&s_w1c[kk * 120 + o0]);
                float a0 = s_act[(i0 + 0) * 400 + kc + kk];
                float a1 = s_act[(i0 + 1) * 400 + kc + kk];
                float a2 = s_act[(i0 + 2) * 400 + kc + kk];
                float a3 = s_act[(i0 + 3) * 400 + kc + kk];
                acc[0]  += a0 * w.x; acc[1]  += a0 * w.y; acc[2]  += a0 * w.z; acc[3]  += a0 * w.w;
                acc[4]  += a1 * w.x; acc[5]  += a1 * w.y; acc[6]  += a1 * w.z; acc[7]  += a1 * w.w;
                acc[8]  += a2 * w.x; acc[9]  += a2 * w.y; acc[10] += a2 * w.z; acc[11] += a2 * w.w;
                acc[12] += a3 * w.x; acc[13] += a3 * w.y; acc[14] += a3 * w.z; acc[15] += a3 * w.w;
            }
        }
    }
    __syncthreads();
    if (tid < 420) {
        #pragma unroll
        for (int ii = 0; ii < 4; ii++)
            #pragma unroll
            for (int oo = 0; oo < 4; oo++)
                s_h1[(i0 + ii) * 120 + o0 + oo] =
                    fmaxf(acc[ii * 4 + oo] + s_b1[o0 + oo], 0.f);
    }
    __syncthreads();

    // ---- fc2: [56,120] x [120,84]^T, 2x2 tiles, strided over 28*42 tiles
    for (int t = tid; t < 28 * 42; t += 512) {
        int ot2 = t % 42, it2 = t / 42;
        int oo0 = ot2 * 2, ii0 = it2 * 2;
        float c00 = s_b2[oo0], c01 = s_b2[oo0 + 1];
        float c10 = s_b2[oo0], c11 = s_b2[oo0 + 1];
        #pragma unroll 4
        for (int k = 0; k < 120; k++) {
            float a0 = s_h1[ii0 * 120 + k];
            float a1 = s_h1[(ii0 + 1) * 120 + k];
            float w0 = s_w2[oo0 * 120 + k];
            float w1 = s_w2[(oo0 + 1) * 120 + k];
            c00 += a0 * w0; c01 += a0 * w1;
            c10 += a1 * w0; c11 += a1 * w1;
        }
        s_h2[ii0 * 84 + oo0]           = fmaxf(c00, 0.f);
        s_h2[ii0 * 84 + oo0 + 1]       = fmaxf(c01, 0.f);
        s_h2[(ii0 + 1) * 84 + oo0]     = fmaxf(c10, 0.f);
        s_h2[(ii0 + 1) * 84 + oo0 + 1] = fmaxf(c11, 0.f);
    }
    __syncthreads();

    // ---- fc3: [56,84] x [84,10]^T -> out
    for (int t = tid; t < GFC * 10; t += 512) {
        int o = t % 10, im = t / 10;
        float a = s_b3[o];
        #pragma unroll 4
        for (int k = 0; k < 84; k++)
            a += s_h2[im * 84 + k] * s_w3[o * 84 + k];
        int gimg = img0 + im;
        if (gimg < NIMG) out[gimg * 10 + o] = a;
    }
}

extern "C" void kernel_launch(void* const* d_in, const int* in_sizes, int n_in,
                              void* d_out, int out_size)
{
    const float* x   = (const float*)d_in[0];
    const float* w1  = (const float*)d_in[1];
    const float* w2  = (const float*)d_in[2];
    const float* fw1 = (const float*)d_in[3];
    const float* fb1 = (const float*)d_in[4];
    const float* fw2 = (const float*)d_in[5];
    const float* fb2 = (const float*)d_in[6];
    const float* fw3 = (const float*)d_in[7];
    const float* fb3 = (const float*)d_in[8];
    float* out = (float*)d_out;

    const int FC_SMEM = (GFC * 400 + 6000 + GFC * 120 + 84 * 120 + GFC * 84 +
                         840 + 120 + 84 + 10 + 16) * (int)sizeof(float);
    cudaFuncSetAttribute(fc_kernel, cudaFuncAttributeMaxDynamicSharedMemorySize,
                         FC_SMEM);

    conv_kernel<<<NIMG, 128>>>(x, w1, w2);
    fc_kernel<<<NBLK_FC, 512, FC_SMEM>>>(fw1, fb1, fw2, fb2, fw3, fb3, out);
}

// round 3
// speedup vs baseline: 1.2642x; 1.2642x over previous
#include <cuda_runtime.h>
#include <cstddef>

#define NIMG 8192
#define GFC 64
#define NBLK_FC (NIMG / GFC)   /* 128 */

// Transposed activations: g_actT[k][img], k in [0,400), img in [0,8192)
__device__ __align__(16) float g_actT[(size_t)400 * NIMG];

// ---------------------------------------------------------------------------
// Kernel 1: fused conv1 -> relu -> pool1 -> conv2 -> relu -> pool2
// One block per image, 128 threads. Live region only:
//   conv1 11x11, pool1 10x10, conv2 6x6, pool2 5x5.
// conv1 uses 2-row x 4-col register tiles (108 tasks = single pass).
// ---------------------------------------------------------------------------
__global__ __launch_bounds__(128) void conv_kernel(const float* __restrict__ x,
                                                   const float* __restrict__ w1,
                                                   const float* __restrict__ w2)
{
    __shared__ __align__(16) float s_w1[450];             // [6][3][5][5]
    __shared__ __align__(16) float s_w2[2400];            // [16][6][5][5]
    __shared__ __align__(16) float s_patch[3][16][16];    // input rows/cols 0..15
    __shared__ __align__(16) float s_c1[6][12][12];       // conv1 relu (pad)
    __shared__ __align__(16) float s_p1[6][10][12];       // pool1 10x10 (pad)
    __shared__ __align__(16) float s_c2[16][6][8];        // conv2 relu 6x6 (pad)

    const int tid = threadIdx.x;
    const int img = blockIdx.x;

    for (int i = tid; i < 450; i += 128) s_w1[i] = w1[i];
    for (int i = tid; i < 2400; i += 128) s_w2[i] = w2[i];

    const float* xb = x + (size_t)img * 3072;
    for (int i = tid; i < 3 * 16 * 16; i += 128) {
        int c = i >> 8;
        int rr = (i & 255) >> 4;
        int cc = i & 15;
        s_patch[c][rr][cc] = xb[c * 1024 + rr * 32 + cc];
    }
    __syncthreads();

    // conv1 + relu: 108 tasks = oc(6) x rowtile(6) x coltile(3); 2 rows x 4 cols
    if (tid < 108) {
        int oc  = tid / 18;
        int rem = tid % 18;
        int rt  = rem / 3;
        int ct  = rem % 3;
        int r0  = rt * 2;
        int c0  = ct * 4;
        float a0[4] = {0.f, 0.f, 0.f, 0.f};
        float a1[4] = {0.f, 0.f, 0.f, 0.f};
        for (int c = 0; c < 3; c++) {
            float p[6][8];
            #pragma unroll
            for (int rr = 0; rr < 6; rr++) {
                float4 v0 = *reinterpret_cast<const float4*>(&s_patch[c][r0 + rr][c0]);
                float4 v1 = *reinterpret_cast<const float4*>(&s_patch[c][r0 + rr][c0 + 4]);
                p[rr][0] = v0.x; p[rr][1] = v0.y; p[rr][2] = v0.z; p[rr][3] = v0.w;
                p[rr][4] = v1.x; p[rr][5] = v1.y; p[rr][6] = v1.z; p[rr][7] = v1.w;
            }
            const float* wb = &s_w1[(oc * 3 + c) * 25];
            #pragma unroll
            for (int u = 0; u < 5; u++) {
                #pragma unroll
                for (int v = 0; v < 5; v++) {
                    float w = wb[u * 5 + v];
                    #pragma unroll
                    for (int j = 0; j < 4; j++) {
                        a0[j] += p[u][v + j] * w;
                        a1[j] += p[u + 1][v + j] * w;
                    }
                }
            }
        }
        #pragma unroll
        for (int j = 0; j < 4; j++) {
            s_c1[oc][r0][c0 + j]     = fmaxf(a0[j], 0.f);   // cols >10 land in pad
            s_c1[oc][r0 + 1][c0 + j] = fmaxf(a1[j], 0.f);   // row 11 lands in pad
        }
    }
    __syncthreads();

    // pool1 (stride-1 2x2 max, top-left 10x10)
    for (int t = tid; t < 600; t += 128) {
        int oc = t / 100;
        int rr = (t % 100) / 10;
        int cc = t % 10;
        float m = fmaxf(fmaxf(s_c1[oc][rr][cc],     s_c1[oc][rr][cc + 1]),
                        fmaxf(s_c1[oc][rr + 1][cc], s_c1[oc][rr + 1][cc + 1]));
        s_p1[oc][rr][cc] = m;
    }
    __syncthreads();

    // conv2 + relu: 96 tasks = oc(16) x row(6), 6 cols each
    if (tid < 96) {
        int oc = tid / 6;
        int r  = tid % 6;
        float acc[6] = {0.f, 0.f, 0.f, 0.f, 0.f, 0.f};
        for (int c = 0; c < 6; c++) {
            #pragma unroll
            for (int u = 0; u < 5; u++) {
                float p[10];
                float4 v0 = *reinterpret_cast<const float4*>(&s_p1[c][r + u][0]);
                float4 v1 = *reinterpret_cast<const float4*>(&s_p1[c][r + u][4]);
                p[0] = v0.x; p[1] = v0.y; p[2] = v0.z; p[3] = v0.w;
                p[4] = v1.x; p[5] = v1.y; p[6] = v1.z; p[7] = v1.w;
                p[8] = s_p1[c][r + u][8];
                p[9] = s_p1[c][r + u][9];
                const float* wp = &s_w2[((oc * 6 + c) * 5 + u) * 5];
                #pragma unroll
                for (int v = 0; v < 5; v++) {
                    float w = wp[v];
                    #pragma unroll
                    for (int xj = 0; xj < 6; xj++) acc[xj] += p[v + xj] * w;
                }
            }
        }
        #pragma unroll
        for (int xj = 0; xj < 6; xj++) s_c2[oc][r][xj] = fmaxf(acc[xj], 0.f);
    }
    __syncthreads();

    // pool2 -> g_actT (transposed: [k][img]); k = oc*25 + i*5 + j
    for (int t = tid; t < 400; t += 128) {
        int oc = t / 25;
        int rr = (t % 25) / 5;
        int cc = t % 5;
        float m = fmaxf(fmaxf(s_c2[oc][rr][cc],     s_c2[oc][rr][cc + 1]),
                        fmaxf(s_c2[oc][rr + 1][cc], s_c2[oc][rr + 1][cc + 1]));
        g_actT[(size_t)t * NIMG + img] = m;
    }
}

// ---------------------------------------------------------------------------
// Kernel 2: fused fc1(relu) -> fc2(relu) -> fc3
// 128 blocks x 512 threads; 64 images per block.
// Acts arrive transposed -> coalesced load, conflict-free float4 LDS.
// fc1: 4img x 4out register tiles (480 threads), w1 streamed in k-chunks of 50.
// ---------------------------------------------------------------------------
#define WCH 50
#define W1STRIDE 124   /* pad: keeps float4 alignment, spreads staging conflicts */

__global__ __launch_bounds__(512) void fc_kernel(const float* __restrict__ fw1,
                                                 const float* __restrict__ fb1,
                                                 const float* __restrict__ fw2,
                                                 const float* __restrict__ fb2,
                                                 const float* __restrict__ fw3,
                                                 const float* __restrict__ fb3,
                                                 float* __restrict__ out)
{
    extern __shared__ __align__(16) float sm[];
    float* s_actT = sm;                        // [400][64]   = 25600
    float* s_w1c  = s_actT + 400 * GFC;        // [50][124]   = 6200
    float* s_h1T  = s_w1c + WCH * W1STRIDE;    // [120][64]   = 7680
    float* s_w2T  = s_h1T + 120 * GFC;         // [120][84]   = 10080
    float* s_h2   = s_w2T + 120 * 84;          // [64][84]    = 5376
    float* s_w3   = s_h2 + GFC * 84;           // [10][84]    = 840
    float* s_b1   = s_w3 + 840;                // 120
    float* s_b2   = s_b1 + 120;                // 84
    float* s_b3   = s_b2 + 84;                 // 12 (pad)

    const int tid  = threadIdx.x;
    const int img0 = blockIdx.x * GFC;

    // acts: coalesced float4 rows of 64 imgs per k
    for (int i = tid; i < 400 * GFC / 4; i += 512) {
        int k  = i / (GFC / 4);
        int i4 = i % (GFC / 4);
        reinterpret_cast<float4*>(&s_actT[k * GFC])[i4] =
            reinterpret_cast<const float4*>(&g_actT[(size_t)k * NIMG + img0])[i4];
    }
    // w2 transposed: [k][84]
    for (int i = tid; i < 120 * 84; i += 512) {
        int k = i / 84, o = i % 84;
        s_w2T[k * 84 + o] = fw2[o * 120 + k];
    }
    for (int i = tid; i < 840; i += 512) s_w3[i] = fw3[i];
    if (tid < 120) s_b1[tid] = fb1[tid];
    if (tid < 84)  s_b2[tid] = fb2[tid];
    if (tid < 10)  s_b3[tid] = fb3[tid];

    // ---- fc1: [64,400] x [400,120]^T, 4x4 tiles, 480 active threads
    const int ot = tid % 30;
    const int it = tid / 30;
    const int o0 = ot * 4;
    const int i0 = it * 4;
    const bool active = (tid < 480);
    float acc[16];
    #pragma unroll
    for (int i = 0; i < 16; i++) acc[i] = 0.f;

    for (int kc = 0; kc < 400; kc += WCH) {
        __syncthreads();   // prev-chunk consumers done (first iter: covers act load)
        // stage w1 chunk transposed: [kk][o], coalesced global reads
        for (int i = tid; i < WCH * 120; i += 512) {
            int o = i / WCH, kk = i % WCH;
            s_w1c[kk * W1STRIDE + o] = fw1[o * 400 + kc + kk];
        }
        __syncthreads();
        if (active) {
            #pragma unroll 5
            for (int kk = 0; kk < WCH; kk++) {
                float4 w = *reinterpret_cast<const float4*>(&s_w1c[kk * W1STRIDE + o0]);
                float4 a = *reinterpret_cast<const float4*>(&s_actT[(kc + kk) * GFC + i0]);
                acc[0]  += a.x * w.x; acc[1]  += a.x * w.y; acc[2]  += a.x * w.z; acc[3]  += a.x * w.w;
                acc[4]  += a.y * w.x; acc[5]  += a.y * w.y; acc[6]  += a.y * w.z; acc[7]  += a.y * w.w;
                acc[8]  += a.z * w.x; acc[9]  += a.z * w.y; acc[10] += a.z * w.z; acc[11] += a.z * w.w;
                acc[12] += a.w * w.x; acc[13] += a.w * w.y; acc[14] += a.w * w.z; acc[15] += a.w * w.w;
            }
        }
    }
    if (active) {
        #pragma unroll
        for (int oo = 0; oo < 4; oo++)
            #pragma unroll
            for (int ii = 0; ii < 4; ii++)
                s_h1T[(o0 + oo) * GFC + i0 + ii] =
                    fmaxf(acc[ii * 4 + oo] + s_b1[o0 + oo], 0.f);
    }
    __syncthreads();

    // ---- fc2: [64,120] x [120,84]^T, 4x4 tiles, 336 active threads
    if (tid < 336) {
        int ot2 = tid % 21;
        int it2 = tid / 21;
        int oo0 = ot2 * 4;
        int ii0 = it2 * 4;
        float c2[16];
        #pragma unroll
        for (int i = 0; i < 16; i++) c2[i] = 0.f;
        #pragma unroll 4
        for (int k = 0; k < 120; k++) {
            float4 a = *reinterpret_cast<const float4*>(&s_h1T[k * GFC + ii0]);
            float4 w = *reinterpret_cast<const float4*>(&s_w2T[k * 84 + oo0]);
            c2[0]  += a.x * w.x; c2[1]  += a.x * w.y; c2[2]  += a.x * w.z; c2[3]  += a.x * w.w;
            c2[4]  += a.y * w.x; c2[5]  += a.y * w.y; c2[6]  += a.y * w.z; c2[7]  += a.y * w.w;
            c2[8]  += a.z * w.x; c2[9]  += a.z * w.y; c2[10] += a.z * w.z; c2[11] += a.z * w.w;
            c2[12] += a.w * w.x; c2[13] += a.w * w.y; c2[14] += a.w * w.z; c2[15] += a.w * w.w;
        }
        #pragma unroll
        for (int ii = 0; ii < 4; ii++)
            #pragma unroll
            for (int oo = 0; oo < 4; oo++)
                s_h2[(ii0 + ii) * 84 + oo0 + oo] =
                    fmaxf(c2[ii * 4 + oo] + s_b2[oo0 + oo], 0.f);
    }
    __syncthreads();

    // ---- fc3: [64,84] x [84,10]^T -> out (coalesced stores)
    for (int t = tid; t < GFC * 10; t += 512) {
        int o  = t % 10;
        int im = t / 10;
        float a = s_b3[o];
        #pragma unroll
        for (int k = 0; k < 84; k += 4) {
            float4 h = *reinterpret_cast<const float4*>(&s_h2[im * 84 + k]);
            float4 w = *reinterpret_cast<const float4*>(&s_w3[o * 84 + k]);
            a += h.x * w.x + h.y * w.y + h.z * w.z + h.w * w.w;
        }
        out[(img0 + im) * 10 + o] = a;
    }
}

extern "C" void kernel_launch(void* const* d_in, const int* in_sizes, int n_in,
                              void* d_out, int out_size)
{
    const float* x   = (const float*)d_in[0];
    const float* w1  = (const float*)d_in[1];
    const float* w2  = (const float*)d_in[2];
    const float* fw1 = (const float*)d_in[3];
    const float* fb1 = (const float*)d_in[4];
    const float* fw2 = (const float*)d_in[5];
    const float* fb2 = (const float*)d_in[6];
    const float* fw3 = (const float*)d_in[7];
    const float* fb3 = (const float*)d_in[8];
    float* out = (float*)d_out;

    const int FC_SMEM = (400 * GFC + WCH * W1STRIDE + 120 * GFC + 120 * 84 +
                         GFC * 84 + 840 + 120 + 84 + 12) * (int)sizeof(float);
    cudaFuncSetAttribute(fc_kernel, cudaFuncAttributeMaxDynamicSharedMemorySize,
                         FC_SMEM);

    conv_kernel<<<NIMG, 128>>>(x, w1, w2);
    fc_kernel<<<NBLK_FC, 512, FC_SMEM>>>(fw1, fb1, fw2, fb2, fw3, fb3, out);
}

// round 4
// speedup vs baseline: 1.4106x; 1.1158x over previous
#include <cuda_runtime.h>
#include <cstddef>

#define NIMG 8192
#define ACT_STRIDE 8256            /* padded: 147*56=8232 <= 8256, 16B-aligned rows */
#define GFC 56
#define NBLK_FC 147                /* 147*56 = 8232 >= 8192 */

// Transposed activations: g_actT[k][img], k in [0,400). Tail imgs stay zero.
__device__ __align__(16) float g_actT[(size_t)400 * ACT_STRIDE];

// ---------------------------------------------------------------------------
// Kernel 1: fused conv1->relu->pool1->conv2->relu->pool2
// WARP-PER-IMAGE: 256 threads = 8 warps = 8 images per block. Each warp runs
// the whole pipeline on its image with only __syncwarp between phases.
// One block barrier at the end for a coalesced transposed store.
// ---------------------------------------------------------------------------
__global__ __launch_bounds__(256) void conv_kernel(const float* __restrict__ x,
                                                   const float* __restrict__ w1,
                                                   const float* __restrict__ w2)
{
    __shared__ __align__(16) float s_w1[456];       // [6][3][5][5]
    __shared__ __align__(16) float s_w2[2400];      // [16][6][5][5]
    __shared__ __align__(16) float s_A[8][768];     // patch [3][16][16] -> p1 [6][10][12]
    __shared__ __align__(16) float s_B[8][880];     // c1 [6][12][12] -> c2 [16][6][8]
    __shared__ __align__(16) float s_out[3200];     // [k=400][img=8]

    const int tid  = threadIdx.x;
    const int wid  = tid >> 5;
    const int lane = tid & 31;
    const int img  = blockIdx.x * 8 + wid;

    for (int i = tid; i < 450; i += 256) s_w1[i] = w1[i];
    for (int i = tid; i < 2400; i += 256) s_w2[i] = w2[i];
    __syncthreads();

    float* A = s_A[wid];
    float* B = s_B[wid];

    // ---- load input patch [3][16][16] (rows/cols 0..15), coalesced in-warp
    const float* xb = x + (size_t)img * 3072;
    for (int i = lane; i < 768; i += 32) {
        int c  = i >> 8;
        int rr = (i >> 4) & 15;
        int cc = i & 15;
        A[i] = xb[c * 1024 + rr * 32 + cc];
    }
    __syncwarp();

    // ---- conv1 + relu: 108 units = oc(6) x rowtile(6,2rows) x coltile(3,4cols)
    for (int u = lane; u < 108; u += 32) {
        int oc  = u / 18;
        int rem = u % 18;
        int r0  = (rem / 3) * 2;
        int c0  = (rem % 3) * 4;
        float a0[4] = {0.f, 0.f, 0.f, 0.f};
        float a1[4] = {0.f, 0.f, 0.f, 0.f};
        for (int c = 0; c < 3; c++) {
            float p[6][8];
            #pragma unroll
            for (int rr = 0; rr < 6; rr++) {
                float4 v0 = *reinterpret_cast<const float4*>(&A[c * 256 + (r0 + rr) * 16 + c0]);
                float4 v1 = *reinterpret_cast<const float4*>(&A[c * 256 + (r0 + rr) * 16 + c0 + 4]);
                p[rr][0] = v0.x; p[rr][1] = v0.y; p[rr][2] = v0.z; p[rr][3] = v0.w;
                p[rr][4] = v1.x; p[rr][5] = v1.y; p[rr][6] = v1.z; p[rr][7] = v1.w;
            }
            const float* wb = &s_w1[(oc * 3 + c) * 25];
            #pragma unroll
            for (int uu = 0; uu < 5; uu++) {
                #pragma unroll
                for (int v = 0; v < 5; v++) {
                    float w = wb[uu * 5 + v];
                    #pragma unroll
                    for (int j = 0; j < 4; j++) {
                        a0[j] += p[uu][v + j] * w;
                        a1[j] += p[uu + 1][v + j] * w;
                    }
                }
            }
        }
        #pragma unroll
        for (int j = 0; j < 4; j++) {
            B[(oc * 12 + r0) * 12 + c0 + j]     = fmaxf(a0[j], 0.f);  // pads absorb overflow
            B[(oc * 12 + r0 + 1) * 12 + c0 + j] = fmaxf(a1[j], 0.f);
        }
    }
    __syncwarp();

    // ---- pool1 (stride-1 2x2, top-left 10x10) -> A as p1[6][10][12]
    for (int t = lane; t < 600; t += 32) {
        int oc = t / 100;
        int rr = (t % 100) / 10;
        int cc = t % 10;
        const float* c1 = &B[(oc * 12 + rr) * 12 + cc];
        float m = fmaxf(fmaxf(c1[0], c1[1]), fmaxf(c1[12], c1[13]));
        A[(oc * 10 + rr) * 12 + cc] = m;
    }
    __syncwarp();

    // ---- conv2 + relu: 96 units = oc(16) x row(6), 6 cols each -> B as c2[16][6][8]
    for (int u = lane; u < 96; u += 32) {
        int oc = u / 6;
        int r  = u % 6;
        float acc[6] = {0.f, 0.f, 0.f, 0.f, 0.f, 0.f};
        for (int c = 0; c < 6; c++) {
            #pragma unroll
            for (int uu = 0; uu < 5; uu++) {
                const float* pr = &A[(c * 10 + r + uu) * 12];
                float p[10];
                float4 v0 = *reinterpret_cast<const float4*>(&pr[0]);
                float4 v1 = *reinterpret_cast<const float4*>(&pr[4]);
                p[0] = v0.x; p[1] = v0.y; p[2] = v0.z; p[3] = v0.w;
                p[4] = v1.x; p[5] = v1.y; p[6] = v1.z; p[7] = v1.w;
                p[8] = pr[8]; p[9] = pr[9];
                const float* wp = &s_w2[((oc * 6 + c) * 5 + uu) * 5];
                #pragma unroll
                for (int v = 0; v < 5; v++) {
                    float w = wp[v];
                    #pragma unroll
                    for (int xj = 0; xj < 6; xj++) acc[xj] += p[v + xj] * w;
                }
            }
        }
        #pragma unroll
        for (int xj = 0; xj < 6; xj++) B[(oc * 6 + r) * 8 + xj] = fmaxf(acc[xj], 0.f);
    }
    __syncwarp();

    // ---- pool2 -> s_out[k][8]
    for (int t = lane; t < 400; t += 32) {
        int oc = t / 25;
        int rr = (t % 25) / 5;
        int cc = t % 5;
        const float* c2 = &B[(oc * 6 + rr) * 8 + cc];
        float m = fmaxf(fmaxf(c2[0], c2[1]), fmaxf(c2[8], c2[9]));
        s_out[t * 8 + wid] = m;
    }
    __syncthreads();

    // ---- coalesced store: per k, 8 contiguous images (32B chunks)
    const int img0 = blockIdx.x * 8;
    for (int k = tid; k < 400; k += 256) {
        float4 v0 = *reinterpret_cast<const float4*>(&s_out[k * 8]);
        float4 v1 = *reinterpret_cast<const float4*>(&s_out[k * 8 + 4]);
        float* dst = &g_actT[(size_t)k * ACT_STRIDE + img0];
        *reinterpret_cast<float4*>(dst)     = v0;
        *reinterpret_cast<float4*>(dst + 4) = v1;
    }
}

// ---------------------------------------------------------------------------
// Kernel 2: fused fc1(relu) -> fc2(relu) -> fc3
// 147 blocks x 512 threads; 56 images per block (full SM coverage).
// w1 streamed in k-chunks of 50 with register prefetch (LDG overlapped with
// compute); inner loop explicitly 2-stage software-pipelined.
// ---------------------------------------------------------------------------
#define WCH 50
#define W1STRIDE 124
#define NPREF 12   /* ceil(6000/512) */

__global__ __launch_bounds__(512) void fc_kernel(const float* __restrict__ fw1,
                                                 const float* __restrict__ fb1,
                                                 const float* __restrict__ fw2,
                                                 const float* __restrict__ fb2,
                                                 const float* __restrict__ fw3,
                                                 const float* __restrict__ fb3,
                                                 float* __restrict__ out)
{
    extern __shared__ __align__(16) float sm[];
    float* s_actT = sm;                        // [400][56]  = 22400
    float* s_w1c  = s_actT + 400 * GFC;        // [50][124]  = 6200
    float* s_h1T  = s_w1c + WCH * W1STRIDE;    // [120][56]  = 6720
    float* s_w2T  = s_h1T + 120 * GFC;         // [120][84]  = 10080
    float* s_h2   = s_w2T + 120 * 84;          // [56][84]   = 4704
    float* s_w3   = s_h2 + GFC * 84;           // [10][84]   = 840
    float* s_b1   = s_w3 + 840;                // 120
    float* s_b2   = s_b1 + 120;                // 84
    float* s_b3   = s_b2 + 84;                 // 12 (pad)

    const int tid  = threadIdx.x;
    const int img0 = blockIdx.x * GFC;

    // acts: coalesced float4 rows of 56 imgs per k (img0 = blk*56, 224B-aligned)
    for (int i = tid; i < 400 * GFC / 4; i += 512) {
        int k  = i / (GFC / 4);
        int i4 = i % (GFC / 4);
        reinterpret_cast<float4*>(&s_actT[k * GFC])[i4] =
            reinterpret_cast<const float4*>(&g_actT[(size_t)k * ACT_STRIDE + img0])[i4];
    }
    for (int i = tid; i < 120 * 84; i += 512) {
        int k = i / 84, o = i % 84;
        s_w2T[k * 84 + o] = fw2[o * 120 + k];
    }
    for (int i = tid; i < 840; i += 512) s_w3[i] = fw3[i];
    if (tid < 120) s_b1[tid] = fb1[tid];
    if (tid < 84)  s_b2[tid] = fb2[tid];
    if (tid < 10)  s_b3[tid] = fb3[tid];

    // ---- fc1: [56,400] x [400,120]^T, 4img x 4out tiles, 420 active threads
    const int o0 = (tid % 30) * 4;
    const int i0 = (tid / 30) * 4;
    const bool active = (tid < 420);
    float acc[16];
    #pragma unroll
    for (int i = 0; i < 16; i++) acc[i] = 0.f;

    // prefetch chunk 0 into registers
    float pref[NPREF];
    #pragma unroll
    for (int j = 0; j < NPREF; j++) {
        int i = tid + j * 512;
        if (i < 6000) pref[j] = fw1[(i / WCH) * 400 + (i % WCH)];
    }

    for (int kc = 0; kc < 400; kc += WCH) {
        __syncthreads();   // consumers of previous chunk done (also fences act load)
        #pragma unroll
        for (int j = 0; j < NPREF; j++) {
            int i = tid + j * 512;
            if (i < 6000) s_w1c[(i % WCH) * W1STRIDE + (i / WCH)] = pref[j];
        }
        if (kc + WCH < 400) {   // issue next chunk's LDGs; they overlap compute
            #pragma unroll
            for (int j = 0; j < NPREF; j++) {
                int i = tid + j * 512;
                if (i < 6000) pref[j] = fw1[(i / WCH) * 400 + (kc + WCH) + (i % WCH)];
            }
        }
        __syncthreads();
        if (active) {
            // 2-stage software pipeline over kk
            float4 w = *reinterpret_cast<const float4*>(&s_w1c[o0]);
            float4 a = *reinterpret_cast<const float4*>(&s_actT[kc * GFC + i0]);
            #pragma unroll 7
            for (int kk = 0; kk < WCH - 1; kk++) {
                float4 wn = *reinterpret_cast<const float4*>(&s_w1c[(kk + 1) * W1STRIDE + o0]);
                float4 an = *reinterpret_cast<const float4*>(&s_actT[(kc + kk + 1) * GFC + i0]);
                acc[0]  += a.x * w.x; acc[1]  += a.x * w.y; acc[2]  += a.x * w.z; acc[3]  += a.x * w.w;
                acc[4]  += a.y * w.x; acc[5]  += a.y * w.y; acc[6]  += a.y * w.z; acc[7]  += a.y * w.w;
                acc[8]  += a.z * w.x; acc[9]  += a.z * w.y; acc[10] += a.z * w.z; acc[11] += a.z * w.w;
                acc[12] += a.w * w.x; acc[13] += a.w * w.y; acc[14] += a.w * w.z; acc[15] += a.w * w.w;
                w = wn; a = an;
            }
            acc[0]  += a.x * w.x; acc[1]  += a.x * w.y; acc[2]  += a.x * w.z; acc[3]  += a.x * w.w;
            acc[4]  += a.y * w.x; acc[5]  += a.y * w.y; acc[6]  += a.y * w.z; acc[7]  += a.y * w.w;
            acc[8]  += a.z * w.x; acc[9]  += a.z * w.y; acc[10] += a.z * w.z; acc[11] += a.z * w.w;
            acc[12] += a.w * w.x; acc[13] += a.w * w.y; acc[14] += a.w * w.z; acc[15] += a.w * w.w;
        }
    }
    if (active) {
        #pragma unroll
        for (int oo = 0; oo < 4; oo++)
            #pragma unroll
            for (int ii = 0; ii < 4; ii++)
                s_h1T[(o0 + oo) * GFC + i0 + ii] =
                    fmaxf(acc[ii * 4 + oo] + s_b1[o0 + oo], 0.f);
    }
    __syncthreads();

    // ---- fc2: [56,120] x [120,84]^T, 4x4 tiles, 294 active threads
    if (tid < 294) {
        int oo0 = (tid % 21) * 4;
        int ii0 = (tid / 21) * 4;
        float c2[16];
        #pragma unroll
        for (int i = 0; i < 16; i++) c2[i] = 0.f;
        #pragma unroll 6
        for (int k = 0; k < 120; k++) {
            float4 a = *reinterpret_cast<const float4*>(&s_h1T[k * GFC + ii0]);
            float4 w = *reinterpret_cast<const float4*>(&s_w2T[k * 84 + oo0]);
            c2[0]  += a.x * w.x; c2[1]  += a.x * w.y; c2[2]  += a.x * w.z; c2[3]  += a.x * w.w;
            c2[4]  += a.y * w.x; c2[5]  += a.y * w.y; c2[6]  += a.y * w.z; c2[7]  += a.y * w.w;
            c2[8]  += a.z * w.x; c2[9]  += a.z * w.y; c2[10] += a.z * w.z; c2[11] += a.z * w.w;
            c2[12] += a.w * w.x; c2[13] += a.w * w.y; c2[14] += a.w * w.z; c2[15] += a.w * w.w;
        }
        #pragma unroll
        for (int ii = 0; ii < 4; ii++)
            #pragma unroll
            for (int oo = 0; oo < 4; oo++)
                s_h2[(ii0 + ii) * 84 + oo0 + oo] =
                    fmaxf(c2[ii * 4 + oo] + s_b2[oo0 + oo], 0.f);
    }
    __syncthreads();

    // ---- fc3: [56,84] x [84,10]^T -> out (guarded tail)
    for (int t = tid; t < GFC * 10; t += 512) {
        int o  = t % 10;
        int im = t / 10;
        float a = s_b3[o];
        #pragma unroll
        for (int k = 0; k < 84; k += 4) {
            float4 h = *reinterpret_cast<const float4*>(&s_h2[im * 84 + k]);
            float4 w = *reinterpret_cast<const float4*>(&s_w3[o * 84 + k]);
            a += h.x * w.x + h.y * w.y + h.z * w.z + h.w * w.w;
        }
        int gimg = img0 + im;
        if (gimg < NIMG) out[gimg * 10 + o] = a;
    }
}

extern "C" void kernel_launch(void* const* d_in, const int* in_sizes, int n_in,
                              void* d_out, int out_size)
{
    const float* x   = (const float*)d_in[0];
    const float* w1  = (const float*)d_in[1];
    const float* w2  = (const float*)d_in[2];
    const float* fw1 = (const float*)d_in[3];
    const float* fb1 = (const float*)d_in[4];
    const float* fw2 = (const float*)d_in[5];
    const float* fb2 = (const float*)d_in[6];
    const float* fw3 = (const float*)d_in[7];
    const float* fb3 = (const float*)d_in[8];
    float* out = (float*)d_out;

    const int FC_SMEM = (400 * GFC + WCH * W1STRIDE + 120 * GFC + 120 * 84 +
                         GFC * 84 + 840 + 120 + 84 + 12) * (int)sizeof(float);
    cudaFuncSetAttribute(fc_kernel, cudaFuncAttributeMaxDynamicSharedMemorySize,
                         FC_SMEM);

    conv_kernel<<<NIMG / 8, 256>>>(x, w1, w2);
    fc_kernel<<<NBLK_FC, 512, FC_SMEM>>>(fw1, fb1, fw2, fb2, fw3, fb3, out);
}

// round 5
// speedup vs baseline: 1.7509x; 1.2412x over previous
#include <cuda_runtime.h>
#include <cstddef>

#define NIMG 8192
#define ACT_STRIDE 8256            /* padded: 147*56=8232 <= 8256, 16B-aligned rows */
#define GFC 56
#define NBLK_FC 147

// Transposed activations: g_actT[k][img], k in [0,400). Tail imgs stay zero.
__device__ __align__(16) float g_actT[(size_t)400 * ACT_STRIDE];

// ---------------------------------------------------------------------------
// Kernel 1: fused conv1->relu->pool1->conv2->relu->pool2
// WARP-PER-IMAGE: 256 threads = 8 warps = 8 images per block.
// conv1: 96 tasks (oc x 4rowtile x 4coltile, 3x3 outputs) = 3 exact passes.
// conv2: 32 tasks (oc x rowhalf, 3x6 outputs) = 1 exact pass, weights in regs.
// ---------------------------------------------------------------------------
__global__ __launch_bounds__(256) void conv_kernel(const float* __restrict__ x,
                                                   const float* __restrict__ w1,
                                                   const float* __restrict__ w2)
{
    __shared__ __align__(16) float s_w1[456];       // [6][3][5][5]
    __shared__ __align__(16) float s_w2[2400];      // [16][6][5][5]
    __shared__ __align__(16) float s_A[8][768];     // patch [3][16][16] -> p1 [6][10][12]
    __shared__ __align__(16) float s_B[8][880];     // c1 [6][12][12] -> c2 [16][6][8]
    __shared__ __align__(16) float s_out[3200];     // [k=400][img=8]

    const int tid  = threadIdx.x;
    const int wid  = tid >> 5;
    const int lane = tid & 31;
    const int img  = blockIdx.x * 8 + wid;

    for (int i = tid; i < 450; i += 256) s_w1[i] = w1[i];
    for (int i = tid; i < 2400; i += 256) s_w2[i] = w2[i];
    __syncthreads();

    float* A = s_A[wid];
    float* B = s_B[wid];

    // ---- load input patch [3][16][16]
    const float* xb = x + (size_t)img * 3072;
    for (int i = lane; i < 768; i += 32) {
        int c  = i >> 8;
        int rr = (i >> 4) & 15;
        int cc = i & 15;
        A[i] = xb[c * 1024 + rr * 32 + cc];
    }
    __syncwarp();

    // ---- conv1 + relu: 96 tasks, each 3 rows x 3 cols; sliding-row form
    #pragma unroll
    for (int pass = 0; pass < 3; pass++) {
        int u   = lane + pass * 32;
        int oc  = u >> 4;
        int rem = u & 15;
        int r0  = (rem >> 2) * 3;
        int c0  = (rem & 3) * 3;
        float acc[3][3];
        #pragma unroll
        for (int i = 0; i < 3; i++)
            #pragma unroll
            for (int j = 0; j < 3; j++) acc[i][j] = 0.f;

        for (int c = 0; c < 3; c++) {
            float wreg[25];
            const float* wb = &s_w1[(oc * 3 + c) * 25];
            #pragma unroll
            for (int i = 0; i < 25; i++) wreg[i] = wb[i];
            const float* Ac = &A[c * 256];
            #pragma unroll
            for (int rr = 0; rr < 7; rr++) {
                float p[7];
                const float* pr = &Ac[(r0 + rr) * 16 + c0];
                #pragma unroll
                for (int j = 0; j < 7; j++) p[j] = pr[j];
                #pragma unroll
                for (int orow = 0; orow < 3; orow++) {
                    int uu = rr - orow;
                    if (uu >= 0 && uu < 5) {
                        #pragma unroll
                        for (int v = 0; v < 5; v++) {
                            float w = wreg[uu * 5 + v];
                            #pragma unroll
                            for (int j = 0; j < 3; j++)
                                acc[orow][j] += p[v + j] * w;
                        }
                    }
                }
            }
        }
        #pragma unroll
        for (int orow = 0; orow < 3; orow++)
            #pragma unroll
            for (int j = 0; j < 3; j++)
                B[(oc * 12 + r0 + orow) * 12 + c0 + j] = fmaxf(acc[orow][j], 0.f);
    }
    __syncwarp();

    // ---- pool1 (stride-1 2x2, top-left 10x10) -> A as p1[6][10][12]
    for (int t = lane; t < 600; t += 32) {
        int oc = t / 100;
        int rr = (t % 100) / 10;
        int cc = t % 10;
        const float* c1 = &B[(oc * 12 + rr) * 12 + cc];
        A[(oc * 10 + rr) * 12 + cc] = fmaxf(fmaxf(c1[0], c1[1]), fmaxf(c1[12], c1[13]));
    }
    __syncwarp();

    // ---- conv2 + relu: 32 tasks = oc(16) x rowhalf(2), 3 rows x 6 cols each
    {
        int oc = lane >> 1;
        int r0 = (lane & 1) * 3;
        float acc[3][6];
        #pragma unroll
        for (int i = 0; i < 3; i++)
            #pragma unroll
            for (int j = 0; j < 6; j++) acc[i][j] = 0.f;

        for (int c = 0; c < 6; c++) {
            float wreg[25];
            const float* wb = &s_w2[(oc * 6 + c) * 25];
            #pragma unroll
            for (int i = 0; i < 25; i++) wreg[i] = wb[i];
            #pragma unroll
            for (int rr = 0; rr < 7; rr++) {
                const float* pr = &A[(c * 10 + r0 + rr) * 12];
                float p[10];
                float4 v0 = *reinterpret_cast<const float4*>(&pr[0]);
                float4 v1 = *reinterpret_cast<const float4*>(&pr[4]);
                p[0] = v0.x; p[1] = v0.y; p[2] = v0.z; p[3] = v0.w;
                p[4] = v1.x; p[5] = v1.y; p[6] = v1.z; p[7] = v1.w;
                p[8] = pr[8]; p[9] = pr[9];
                #pragma unroll
                for (int orow = 0; orow < 3; orow++) {
                    int uu = rr - orow;
                    if (uu >= 0 && uu < 5) {
                        #pragma unroll
                        for (int v = 0; v < 5; v++) {
                            float w = wreg[uu * 5 + v];
                            #pragma unroll
                            for (int j = 0; j < 6; j++)
                                acc[orow][j] += p[v + j] * w;
                        }
                    }
                }
            }
        }
        #pragma unroll
        for (int orow = 0; orow < 3; orow++)
            #pragma unroll
            for (int j = 0; j < 6; j++)
                B[(oc * 6 + r0 + orow) * 8 + j] = fmaxf(acc[orow][j], 0.f);
    }
    __syncwarp();

    // ---- pool2 -> s_out[k][8]
    for (int t = lane; t < 400; t += 32) {
        int oc = t / 25;
        int rr = (t % 25) / 5;
        int cc = t % 5;
        const float* c2 = &B[(oc * 6 + rr) * 8 + cc];
        s_out[t * 8 + wid] = fmaxf(fmaxf(c2[0], c2[1]), fmaxf(c2[8], c2[9]));
    }
    __syncthreads();

    // ---- coalesced transposed store: per k, 8 contiguous images
    const int img0 = blockIdx.x * 8;
    for (int k = tid; k < 400; k += 256) {
        float4 v0 = *reinterpret_cast<const float4*>(&s_out[k * 8]);
        float4 v1 = *reinterpret_cast<const float4*>(&s_out[k * 8 + 4]);
        float* dst = &g_actT[(size_t)k * ACT_STRIDE + img0];
        *reinterpret_cast<float4*>(dst)     = v0;
        *reinterpret_cast<float4*>(dst + 4) = v1;
    }
}

// ---------------------------------------------------------------------------
// Kernel 2: fused fc1(relu) -> fc2(relu) -> fc3
// 147 blocks x 512 threads; 56 images per block.
// w1 double-buffered in smem (1 barrier/chunk, STS overlaps FMA);
// w2T aliases the w1 buffers, h2 aliases actT -> 170 KB total.
// ---------------------------------------------------------------------------
#define WCH 50
#define W1STRIDE 124
#define NPREF 12   /* ceil(6000/512) */
#define NCHUNK 8

__global__ __launch_bounds__(512) void fc_kernel(const float* __restrict__ fw1,
                                                 const float* __restrict__ fb1,
                                                 const float* __restrict__ fw2,
                                                 const float* __restrict__ fb2,
                                                 const float* __restrict__ fw3,
                                                 const float* __restrict__ fb3,
                                                 float* __restrict__ out)
{
    extern __shared__ __align__(16) float sm[];
    float* s_actT = sm;                          // [400][56] = 22400 (later: h2)
    float* s_w1c  = s_actT + 400 * GFC;          // 2 x [50][124] = 12400 (later: w2T)
    float* s_h1T  = s_w1c + 2 * WCH * W1STRIDE;  // [120][56] = 6720
    float* s_w3   = s_h1T + 120 * GFC;           // 840
    float* s_b1   = s_w3 + 840;                  // 120
    float* s_b2   = s_b1 + 120;                  // 84
    float* s_b3   = s_b2 + 84;                   // 12 (pad)
    float* s_w2T  = s_w1c;                       // alias (after fc1)
    float* s_h2   = s_actT;                      // alias (after fc1): [56][84]

    const int tid  = threadIdx.x;
    const int img0 = blockIdx.x * GFC;

    // acts: coalesced float4 rows of 56 imgs per k
    for (int i = tid; i < 400 * GFC / 4; i += 512) {
        int k  = i / (GFC / 4);
        int i4 = i % (GFC / 4);
        reinterpret_cast<float4*>(&s_actT[k * GFC])[i4] =
            reinterpret_cast<const float4*>(&g_actT[(size_t)k * ACT_STRIDE + img0])[i4];
    }
    for (int i = tid; i < 840; i += 512) s_w3[i] = fw3[i];
    if (tid < 120) s_b1[tid] = fb1[tid];
    if (tid < 84)  s_b2[tid] = fb2[tid];
    if (tid < 10)  s_b3[tid] = fb3[tid];

    // ---- fc1: [56,400] x [400,120]^T, 4img x 4out tiles, 420 active threads
    const int o0 = (tid % 30) * 4;
    const int i0 = (tid / 30) * 4;
    const bool active = (tid < 420);
    float acc[16];
    #pragma unroll
    for (int i = 0; i < 16; i++) acc[i] = 0.f;

    float pref[NPREF];
    // chunk 0 -> regs -> buf0; chunk 1 -> regs
    #pragma unroll
    for (int j = 0; j < NPREF; j++) {
        int i = tid + j * 512;
        if (i < 6000) pref[j] = fw1[(i / WCH) * 400 + (i % WCH)];
    }
    #pragma unroll
    for (int j = 0; j < NPREF; j++) {
        int i = tid + j * 512;
        if (i < 6000) s_w1c[(i % WCH) * W1STRIDE + (i / WCH)] = pref[j];
    }
    #pragma unroll
    for (int j = 0; j < NPREF; j++) {
        int i = tid + j * 512;
        if (i < 6000) pref[j] = fw1[(i / WCH) * 400 + WCH + (i % WCH)];
    }
    __syncthreads();

    for (int ch = 0; ch < NCHUNK; ch++) {
        const int kc = ch * WCH;
        const float* wbuf = s_w1c + (ch & 1) * (WCH * W1STRIDE);
        if (active) {
            float4 w = *reinterpret_cast<const float4*>(&wbuf[o0]);
            float4 a = *reinterpret_cast<const float4*>(&s_actT[kc * GFC + i0]);
            #pragma unroll 7
            for (int kk = 0; kk < WCH - 1; kk++) {
                float4 wn = *reinterpret_cast<const float4*>(&wbuf[(kk + 1) * W1STRIDE + o0]);
                float4 an = *reinterpret_cast<const float4*>(&s_actT[(kc + kk + 1) * GFC + i0]);
                acc[0]  += a.x * w.x; acc[1]  += a.x * w.y; acc[2]  += a.x * w.z; acc[3]  += a.x * w.w;
                acc[4]  += a.y * w.x; acc[5]  += a.y * w.y; acc[6]  += a.y * w.z; acc[7]  += a.y * w.w;
                acc[8]  += a.z * w.x; acc[9]  += a.z * w.y; acc[10] += a.z * w.z; acc[11] += a.z * w.w;
                acc[12] += a.w * w.x; acc[13] += a.w * w.y; acc[14] += a.w * w.z; acc[15] += a.w * w.w;
                w = wn; a = an;
            }
            acc[0]  += a.x * w.x; acc[1]  += a.x * w.y; acc[2]  += a.x * w.z; acc[3]  += a.x * w.w;
            acc[4]  += a.y * w.x; acc[5]  += a.y * w.y; acc[6]  += a.y * w.z; acc[7]  += a.y * w.w;
            acc[8]  += a.z * w.x; acc[9]  += a.z * w.y; acc[10] += a.z * w.z; acc[11] += a.z * w.w;
            acc[12] += a.w * w.x; acc[13] += a.w * w.y; acc[14] += a.w * w.z; acc[15] += a.w * w.w;
        }
        if (ch < NCHUNK - 1) {
            float* nbuf = s_w1c + ((ch + 1) & 1) * (WCH * W1STRIDE);
            #pragma unroll
            for (int j = 0; j < NPREF; j++) {
                int i = tid + j * 512;
                if (i < 6000) nbuf[(i % WCH) * W1STRIDE + (i / WCH)] = pref[j];
            }
            if (ch < NCHUNK - 2) {
                #pragma unroll
                for (int j = 0; j < NPREF; j++) {
                    int i = tid + j * 512;
                    if (i < 6000) pref[j] = fw1[(i / WCH) * 400 + (kc + 2 * WCH) + (i % WCH)];
                }
            }
        }
        __syncthreads();
    }
    if (active) {
        #pragma unroll
        for (int oo = 0; oo < 4; oo++)
            #pragma unroll
            for (int ii = 0; ii < 4; ii++)
                s_h1T[(o0 + oo) * GFC + i0 + ii] =
                    fmaxf(acc[ii * 4 + oo] + s_b1[o0 + oo], 0.f);
    }
    // stage w2 transposed into the (now free) w1 buffers
    for (int i = tid; i < 120 * 84; i += 512) {
        int k = i / 84, o = i % 84;
        s_w2T[k * 84 + o] = fw2[o * 120 + k];
    }
    __syncthreads();

    // ---- fc2: [56,120] x [120,84]^T, 4x4 tiles, 294 active threads
    if (tid < 294) {
        int oo0 = (tid % 21) * 4;
        int ii0 = (tid / 21) * 4;
        float c2[16];
        #pragma unroll
        for (int i = 0; i < 16; i++) c2[i] = 0.f;
        #pragma unroll 6
        for (int k = 0; k < 120; k++) {
            float4 a = *reinterpret_cast<const float4*>(&s_h1T[k * GFC + ii0]);
            float4 w = *reinterpret_cast<const float4*>(&s_w2T[k * 84 + oo0]);
            c2[0]  += a.x * w.x; c2[1]  += a.x * w.y; c2[2]  += a.x * w.z; c2[3]  += a.x * w.w;
            c2[4]  += a.y * w.x; c2[5]  += a.y * w.y; c2[6]  += a.y * w.z; c2[7]  += a.y * w.w;
            c2[8]  += a.z * w.x; c2[9]  += a.z * w.y; c2[10] += a.z * w.z; c2[11] += a.z * w.w;
            c2[12] += a.w * w.x; c2[13] += a.w * w.y; c2[14] += a.w * w.z; c2[15] += a.w * w.w;
        }
        #pragma unroll
        for (int ii = 0; ii < 4; ii++)
            #pragma unroll
            for (int oo = 0; oo < 4; oo++)
                s_h2[(ii0 + ii) * 84 + oo0 + oo] =
                    fmaxf(c2[ii * 4 + oo] + s_b2[oo0 + oo], 0.f);
    }
    __syncthreads();

    // ---- fc3: [56,84] x [84,10]^T -> out
    for (int t = tid; t < GFC * 10; t += 512) {
        int o  = t % 10;
        int im = t / 10;
        float a = s_b3[o];
        #pragma unroll
        for (int k = 0; k < 84; k += 4) {
            float4 h = *reinterpret_cast<const float4*>(&s_h2[im * 84 + k]);
            float4 w = *reinterpret_cast<const float4*>(&s_w3[o * 84 + k]);
            a += h.x * w.x + h.y * w.y + h.z * w.z + h.w * w.w;
        }
        int gimg = img0 + im;
        if (gimg < NIMG) out[gimg * 10 + o] = a;
    }
}

extern "C" void kernel_launch(void* const* d_in, const int* in_sizes, int n_in,
                              void* d_out, int out_size)
{
    const float* x   = (const float*)d_in[0];
    const float* w1  = (const float*)d_in[1];
    const float* w2  = (const float*)d_in[2];
    const float* fw1 = (const float*)d_in[3];
    const float* fb1 = (const float*)d_in[4];
    const float* fw2 = (const float*)d_in[5];
    const float* fb2 = (const float*)d_in[6];
    const float* fw3 = (const float*)d_in[7];
    const float* fb3 = (const float*)d_in[8];
    float* out = (float*)d_out;

    const int FC_SMEM = (400 * GFC + 2 * WCH * W1STRIDE + 120 * GFC +
                         840 + 120 + 84 + 12) * (int)sizeof(float);
    cudaFuncSetAttribute(fc_kernel, cudaFuncAttributeMaxDynamicSharedMemorySize,
                         FC_SMEM);

    conv_kernel<<<NIMG / 8, 256>>>(x, w1, w2);
    fc_kernel<<<NBLK_FC, 512, FC_SMEM>>>(fw1, fb1, fw2, fb2, fw3, fb3, out);
}

// round 6
// speedup vs baseline: 1.7886x; 1.0215x over previous
#include <cuda_runtime.h>
#include <cstddef>

#define NIMG 8192
#define ACT_STRIDE 8256            /* >= 293*28 = 8204; 16B-aligned rows */
#define GFC 28
#define NBLK_FC 293                /* 293*28 = 8204 >= 8192 */

// Transposed activations: g_actT[k][img], k in [0,400). Tail stays zero.
__device__ __align__(16) float g_actT[(size_t)400 * ACT_STRIDE];

// ---------------------------------------------------------------------------
// Kernel 1: fused conv1->relu->pool1->conv2->relu->pool2  (unchanged, ~floor)
// WARP-PER-IMAGE: 256 threads = 8 warps = 8 images per block.
// ---------------------------------------------------------------------------
__global__ __launch_bounds__(256) void conv_kernel(const float* __restrict__ x,
                                                   const float* __restrict__ w1,
                                                   const float* __restrict__ w2)
{
    __shared__ __align__(16) float s_w1[456];
    __shared__ __align__(16) float s_w2[2400];
    __shared__ __align__(16) float s_A[8][768];
    __shared__ __align__(16) float s_B[8][880];
    __shared__ __align__(16) float s_out[3200];

    const int tid  = threadIdx.x;
    const int wid  = tid >> 5;
    const int lane = tid & 31;
    const int img  = blockIdx.x * 8 + wid;

    for (int i = tid; i < 450; i += 256) s_w1[i] = w1[i];
    for (int i = tid; i < 2400; i += 256) s_w2[i] = w2[i];
    __syncthreads();

    float* A = s_A[wid];
    float* B = s_B[wid];

    const float* xb = x + (size_t)img * 3072;
    for (int i = lane; i < 768; i += 32) {
        int c  = i >> 8;
        int rr = (i >> 4) & 15;
        int cc = i & 15;
        A[i] = xb[c * 1024 + rr * 32 + cc];
    }
    __syncwarp();

    // conv1 + relu: 96 tasks, each 3x3 outputs; sliding-row form
    #pragma unroll
    for (int pass = 0; pass < 3; pass++) {
        int u   = lane + pass * 32;
        int oc  = u >> 4;
        int rem = u & 15;
        int r0  = (rem >> 2) * 3;
        int c0  = (rem & 3) * 3;
        float acc[3][3];
        #pragma unroll
        for (int i = 0; i < 3; i++)
            #pragma unroll
            for (int j = 0; j < 3; j++) acc[i][j] = 0.f;

        for (int c = 0; c < 3; c++) {
            float wreg[25];
            const float* wb = &s_w1[(oc * 3 + c) * 25];
            #pragma unroll
            for (int i = 0; i < 25; i++) wreg[i] = wb[i];
            const float* Ac = &A[c * 256];
            #pragma unroll
            for (int rr = 0; rr < 7; rr++) {
                float p[7];
                const float* pr = &Ac[(r0 + rr) * 16 + c0];
                #pragma unroll
                for (int j = 0; j < 7; j++) p[j] = pr[j];
                #pragma unroll
                for (int orow = 0; orow < 3; orow++) {
                    int uu = rr - orow;
                    if (uu >= 0 && uu < 5) {
                        #pragma unroll
                        for (int v = 0; v < 5; v++) {
                            float w = wreg[uu * 5 + v];
                            #pragma unroll
                            for (int j = 0; j < 3; j++)
                                acc[orow][j] += p[v + j] * w;
                        }
                    }
                }
            }
        }
        #pragma unroll
        for (int orow = 0; orow < 3; orow++)
            #pragma unroll
            for (int j = 0; j < 3; j++)
                B[(oc * 12 + r0 + orow) * 12 + c0 + j] = fmaxf(acc[orow][j], 0.f);
    }
    __syncwarp();

    for (int t = lane; t < 600; t += 32) {
        int oc = t / 100;
        int rr = (t % 100) / 10;
        int cc = t % 10;
        const float* c1 = &B[(oc * 12 + rr) * 12 + cc];
        A[(oc * 10 + rr) * 12 + cc] = fmaxf(fmaxf(c1[0], c1[1]), fmaxf(c1[12], c1[13]));
    }
    __syncwarp();

    // conv2 + relu: 32 tasks = oc(16) x rowhalf(2), weights in regs
    {
        int oc = lane >> 1;
        int r0 = (lane & 1) * 3;
        float acc[3][6];
        #pragma unroll
        for (int i = 0; i < 3; i++)
            #pragma unroll
            for (int j = 0; j < 6; j++) acc[i][j] = 0.f;

        for (int c = 0; c < 6; c++) {
            float wreg[25];
            const float* wb = &s_w2[(oc * 6 + c) * 25];
            #pragma unroll
            for (int i = 0; i < 25; i++) wreg[i] = wb[i];
            #pragma unroll
            for (int rr = 0; rr < 7; rr++) {
                const float* pr = &A[(c * 10 + r0 + rr) * 12];
                float p[10];
                float4 v0 = *reinterpret_cast<const float4*>(&pr[0]);
                float4 v1 = *reinterpret_cast<const float4*>(&pr[4]);
                p[0] = v0.x; p[1] = v0.y; p[2] = v0.z; p[3] = v0.w;
                p[4] = v1.x; p[5] = v1.y; p[6] = v1.z; p[7] = v1.w;
                p[8] = pr[8]; p[9] = pr[9];
                #pragma unroll
                for (int orow = 0; orow < 3; orow++) {
                    int uu = rr - orow;
                    if (uu >= 0 && uu < 5) {
                        #pragma unroll
                        for (int v = 0; v < 5; v++) {
                            float w = wreg[uu * 5 + v];
                            #pragma unroll
                            for (int j = 0; j < 6; j++)
                                acc[orow][j] += p[v + j] * w;
                        }
                    }
                }
            }
        }
        #pragma unroll
        for (int orow = 0; orow < 3; orow++)
            #pragma unroll
            for (int j = 0; j < 6; j++)
                B[(oc * 6 + r0 + orow) * 8 + j] = fmaxf(acc[orow][j], 0.f);
    }
    __syncwarp();

    for (int t = lane; t < 400; t += 32) {
        int oc = t / 25;
        int rr = (t % 25) / 5;
        int cc = t % 5;
        const float* c2 = &B[(oc * 6 + rr) * 8 + cc];
        s_out[t * 8 + wid] = fmaxf(fmaxf(c2[0], c2[1]), fmaxf(c2[8], c2[9]));
    }
    __syncthreads();

    const int img0 = blockIdx.x * 8;
    for (int k = tid; k < 400; k += 256) {
        float4 v0 = *reinterpret_cast<const float4*>(&s_out[k * 8]);
        float4 v1 = *reinterpret_cast<const float4*>(&s_out[k * 8 + 4]);
        float* dst = &g_actT[(size_t)k * ACT_STRIDE + img0];
        *reinterpret_cast<float4*>(dst)     = v0;
        *reinterpret_cast<float4*>(dst + 4) = v1;
    }
}

// ---------------------------------------------------------------------------
// Kernel 2: fused fc1(relu) -> fc2(relu) -> fc3
// 293 blocks x 256 threads; 28 images per block; ~88 KB smem -> 2 blocks/SM.
// Both acts and w1 double-buffered in k-chunks of 25 with register prefetch;
// one barrier per chunk. h2 aliases the w1 buffers after fc1.
// ---------------------------------------------------------------------------
#define WCH 25
#define NCHUNK 16
#define W1STRIDE 124
#define NPREFW 12   /* ceil(25*120/256) */
#define NPREFA 3    /* ceil(25*28/256)  */

__global__ __launch_bounds__(256, 2) void fc_kernel(const float* __restrict__ fw1,
                                                    const float* __restrict__ fb1,
                                                    const float* __restrict__ fw2,
                                                    const float* __restrict__ fb2,
                                                    const float* __restrict__ fw3,
                                                    const float* __restrict__ fb3,
                                                    float* __restrict__ out)
{
    extern __shared__ __align__(16) float sm[];
    float* s_act  = sm;                           // 2 x [25][28]  = 1400
    float* s_w1c  = s_act + 2 * WCH * GFC;        // 2 x [25][124] = 6200
    float* s_h1T  = s_w1c + 2 * WCH * W1STRIDE;   // [120][28]     = 3360
    float* s_w2T  = s_h1T + 120 * GFC;            // [120][84]     = 10080
    float* s_w3   = s_w2T + 120 * 84;             // 840
    float* s_b1   = s_w3 + 840;                   // 120
    float* s_b2   = s_b1 + 120;                   // 84
    float* s_b3   = s_b2 + 84;                    // 12 (pad)
    float* s_h2   = s_w1c;                        // alias after fc1: [28][84]

    const int tid  = threadIdx.x;
    const int img0 = blockIdx.x * GFC;

    // w2 transposed (coalesced LDG, scattered STS), w3, biases
    for (int i = tid; i < 120 * 84; i += 256) {
        int o = i / 120, k = i % 120;
        s_w2T[k * 84 + o] = fw2[i];
    }
    for (int i = tid; i < 840; i += 256) s_w3[i] = fw3[i];
    if (tid < 120) s_b1[tid] = fb1[tid];
    else if (tid < 204) s_b2[tid - 120] = fb2[tid - 120];
    else if (tid < 214) s_b3[tid - 204] = fb3[tid - 204];

    // ---- fc1: [28,400] x [400,120]^T, 4img x 4out tiles, 210 active threads
    const int o0 = (tid % 30) * 4;
    const int i0 = (tid / 30) * 4;
    const bool active = (tid < 210);
    float acc[16];
    #pragma unroll
    for (int i = 0; i < 16; i++) acc[i] = 0.f;

    float prw[NPREFW];
    float pra[NPREFA];

    // chunk 0 -> regs -> buf0
    #pragma unroll
    for (int j = 0; j < NPREFW; j++) {
        int i = tid + j * 256;
        if (i < 3000) prw[j] = fw1[(i / WCH) * 400 + (i % WCH)];
    }
    #pragma unroll
    for (int j = 0; j < NPREFA; j++) {
        int i = tid + j * 256;
        if (i < 700) pra[j] = g_actT[(size_t)(i / GFC) * ACT_STRIDE + img0 + (i % GFC)];
    }
    #pragma unroll
    for (int j = 0; j < NPREFW; j++) {
        int i = tid + j * 256;
        if (i < 3000) s_w1c[(i % WCH) * W1STRIDE + (i / WCH)] = prw[j];
    }
    #pragma unroll
    for (int j = 0; j < NPREFA; j++) {
        int i = tid + j * 256;
        if (i < 700) s_act[i] = pra[j];
    }
    // chunk 1 -> regs
    #pragma unroll
    for (int j = 0; j < NPREFW; j++) {
        int i = tid + j * 256;
        if (i < 3000) prw[j] = fw1[(i / WCH) * 400 + WCH + (i % WCH)];
    }
    #pragma unroll
    for (int j = 0; j < NPREFA; j++) {
        int i = tid + j * 256;
        if (i < 700) pra[j] = g_actT[(size_t)(WCH + i / GFC) * ACT_STRIDE + img0 + (i % GFC)];
    }
    __syncthreads();

    for (int ch = 0; ch < NCHUNK; ch++) {
        const float* wbuf = s_w1c + (ch & 1) * (WCH * W1STRIDE);
        const float* abuf = s_act + (ch & 1) * (WCH * GFC);
        if (active) {
            float4 w = *reinterpret_cast<const float4*>(&wbuf[o0]);
            float4 a = *reinterpret_cast<const float4*>(&abuf[i0]);
            #pragma unroll
            for (int kk = 0; kk < WCH - 1; kk++) {
                float4 wn = *reinterpret_cast<const float4*>(&wbuf[(kk + 1) * W1STRIDE + o0]);
                float4 an = *reinterpret_cast<const float4*>(&abuf[(kk + 1) * GFC + i0]);
                acc[0]  += a.x * w.x; acc[1]  += a.x * w.y; acc[2]  += a.x * w.z; acc[3]  += a.x * w.w;
                acc[4]  += a.y * w.x; acc[5]  += a.y * w.y; acc[6]  += a.y * w.z; acc[7]  += a.y * w.w;
                acc[8]  += a.z * w.x; acc[9]  += a.z * w.y; acc[10] += a.z * w.z; acc[11] += a.z * w.w;
                acc[12] += a.w * w.x; acc[13] += a.w * w.y; acc[14] += a.w * w.z; acc[15] += a.w * w.w;
                w = wn; a = an;
            }
            acc[0]  += a.x * w.x; acc[1]  += a.x * w.y; acc[2]  += a.x * w.z; acc[3]  += a.x * w.w;
            acc[4]  += a.y * w.x; acc[5]  += a.y * w.y; acc[6]  += a.y * w.z; acc[7]  += a.y * w.w;
            acc[8]  += a.z * w.x; acc[9]  += a.z * w.y; acc[10] += a.z * w.z; acc[11] += a.z * w.w;
            acc[12] += a.w * w.x; acc[13] += a.w * w.y; acc[14] += a.w * w.z; acc[15] += a.w * w.w;
        }
        if (ch < NCHUNK - 1) {
            float* nw = s_w1c + ((ch + 1) & 1) * (WCH * W1STRIDE);
            float* na = s_act + ((ch + 1) & 1) * (WCH * GFC);
            #pragma unroll
            for (int j = 0; j < NPREFW; j++) {
                int i = tid + j * 256;
                if (i < 3000) nw[(i % WCH) * W1STRIDE + (i / WCH)] = prw[j];
            }
            #pragma unroll
            for (int j = 0; j < NPREFA; j++) {
                int i = tid + j * 256;
                if (i < 700) na[i] = pra[j];
            }
            if (ch < NCHUNK - 2) {
                const int kb = (ch + 2) * WCH;
                #pragma unroll
                for (int j = 0; j < NPREFW; j++) {
                    int i = tid + j * 256;
                    if (i < 3000) prw[j] = fw1[(i / WCH) * 400 + kb + (i % WCH)];
                }
                #pragma unroll
                for (int j = 0; j < NPREFA; j++) {
                    int i = tid + j * 256;
                    if (i < 700) pra[j] = g_actT[(size_t)(kb + i / GFC) * ACT_STRIDE + img0 + (i % GFC)];
                }
            }
        }
        __syncthreads();
    }
    if (active) {
        #pragma unroll
        for (int oo = 0; oo < 4; oo++)
            #pragma unroll
            for (int ii = 0; ii < 4; ii++)
                s_h1T[(o0 + oo) * GFC + i0 + ii] =
                    fmaxf(acc[ii * 4 + oo] + s_b1[o0 + oo], 0.f);
    }
    __syncthreads();

    // ---- fc2: [28,120] x [120,84]^T, 4x4 tiles, 147 active threads
    if (tid < 147) {
        int oo0 = (tid % 21) * 4;
        int ii0 = (tid / 21) * 4;
        float c2[16];
        #pragma unroll
        for (int i = 0; i < 16; i++) c2[i] = 0.f;
        #pragma unroll 6
        for (int k = 0; k < 120; k++) {
            float4 a = *reinterpret_cast<const float4*>(&s_h1T[k * GFC + ii0]);
            float4 w = *reinterpret_cast<const float4*>(&s_w2T[k * 84 + oo0]);
            c2[0]  += a.x * w.x; c2[1]  += a.x * w.y; c2[2]  += a.x * w.z; c2[3]  += a.x * w.w;
            c2[4]  += a.y * w.x; c2[5]  += a.y * w.y; c2[6]  += a.y * w.z; c2[7]  += a.y * w.w;
            c2[8]  += a.z * w.x; c2[9]  += a.z * w.y; c2[10] += a.z * w.z; c2[11] += a.z * w.w;
            c2[12] += a.w * w.x; c2[13] += a.w * w.y; c2[14] += a.w * w.z; c2[15] += a.w * w.w;
        }
        #pragma unroll
        for (int ii = 0; ii < 4; ii++)
            #pragma unroll
            for (int oo = 0; oo < 4; oo++)
                s_h2[(ii0 + ii) * 84 + oo0 + oo] =
                    fmaxf(c2[ii * 4 + oo] + s_b2[oo0 + oo], 0.f);
    }
    __syncthreads();

    // ---- fc3: [28,84] x [84,10]^T -> out (guarded tail)
    for (int t = tid; t < GFC * 10; t += 256) {
        int o  = t % 10;
        int im = t / 10;
        float a = s_b3[o];
        #pragma unroll
        for (int k = 0; k < 84; k += 4) {
            float4 h = *reinterpret_cast<const float4*>(&s_h2[im * 84 + k]);
            float4 w = *reinterpret_cast<const float4*>(&s_w3[o * 84 + k]);
            a += h.x * w.x + h.y * w.y + h.z * w.z + h.w * w.w;
        }
        int gimg = img0 + im;
        if (gimg < NIMG) out[gimg * 10 + o] = a;
    }
}

extern "C" void kernel_launch(void* const* d_in, const int* in_sizes, int n_in,
                              void* d_out, int out_size)
{
    const float* x   = (const float*)d_in[0];
    const float* w1  = (const float*)d_in[1];
    const float* w2  = (const float*)d_in[2];
    const float* fw1 = (const float*)d_in[3];
    const float* fb1 = (const float*)d_in[4];
    const float* fw2 = (const float*)d_in[5];
    const float* fb2 = (const float*)d_in[6];
    const float* fw3 = (const float*)d_in[7];
    const float* fb3 = (const float*)d_in[8];
    float* out = (float*)d_out;

    const int FC_SMEM = (2 * WCH * GFC + 2 * WCH * W1STRIDE + 120 * GFC +
                         120 * 84 + 840 + 120 + 84 + 12) * (int)sizeof(float);
    cudaFuncSetAttribute(fc_kernel, cudaFuncAttributeMaxDynamicSharedMemorySize,
                         FC_SMEM);

    conv_kernel<<<NIMG / 8, 256>>>(x, w1, w2);
    fc_kernel<<<NBLK_FC, 256, FC_SMEM>>>(fw1, fb1, fw2, fb2, fw3, fb3, out);
}